// round 16
// baseline (speedup 1.0000x reference)
#include <cuda_runtime.h>
#include <cstdint>

#define N_NODES 100000
#define N_EDGES 1600000
#define F 64

// ---------------- static device scratch ----------------
// g_deg is zero at module load and re-zeroed by k_scan_finish after use,
// so it is zero at entry of EVERY kernel_launch call (no memset needed).
__device__ int   g_deg[N_NODES];
__device__ int   g_off[N_NODES + 1];
__device__ int   g_cursor[N_NODES];
__device__ int   g_bsum[128];
__device__ int2  g_csr[N_EDGES];              // packed {src, float_bits(e)}
__device__ float g_deginv[N_NODES];
__device__ float g_hN[(size_t)N_NODES * F];   // hN (layer1) -> tp2 (layer2, in-place)
__device__ float g_P[(size_t)N_NODES * F];    // P = in@W1_top + b1 (overlapped)

// ---------------- helpers ----------------
__device__ __forceinline__ void pdl_wait() {
    asm volatile("griddepcontrol.wait;" ::: "memory");
}
__device__ __forceinline__ unsigned long long pack2(float a) {
    unsigned long long r;
    asm("mov.b64 %0, {%1, %1};" : "=l"(r) : "f"(a));
    return r;
}
__device__ __forceinline__ void ffma2(unsigned long long& d,
                                      unsigned long long a, unsigned long long b) {
    asm("fma.rn.f32x2 %0, %1, %2, %0;" : "+l"(d) : "l"(a), "l"(b));
}
__device__ __forceinline__ float2 unpack2(unsigned long long v) {
    float lo, hi;
    asm("mov.b64 {%0, %1}, %2;" : "=f"(lo), "=f"(hi) : "l"(v));
    return make_float2(lo, hi);
}

// ---------------- CSR build ----------------
__global__ void k_deg(const int4* __restrict__ dst4) {
    int i = blockIdx.x * blockDim.x + threadIdx.x;
    if (i < N_EDGES / 4) {
        int4 d = dst4[i];
        atomicAdd(&g_deg[d.x], 1);
        atomicAdd(&g_deg[d.y], 1);
        atomicAdd(&g_deg[d.z], 1);
        atomicAdd(&g_deg[d.w], 1);
    }
}

// warp-shuffle scan (2 syncthreads). PDL: waits before reading g_deg.
__global__ void __launch_bounds__(1024) k_scan_local() {
    __shared__ int wsum[32];
    int i = blockIdx.x * 1024 + threadIdx.x;
    int lane = threadIdx.x & 31, wid = threadIdx.x >> 5;
    pdl_wait();                       // dep: k_deg writes g_deg
    int v = (i < N_NODES) ? g_deg[i] : 0;
    int x = v;
#pragma unroll
    for (int o = 1; o < 32; o <<= 1) {
        int y = __shfl_up_sync(0xffffffff, x, o);
        if (lane >= o) x += y;
    }
    if (lane == 31) wsum[wid] = x;
    __syncthreads();
    if (wid == 0) {
        int s = wsum[lane];
#pragma unroll
        for (int o = 1; o < 32; o <<= 1) {
            int y = __shfl_up_sync(0xffffffff, s, o);
            if (lane >= o) s += y;
        }
        wsum[lane] = s;
    }
    __syncthreads();
    int incl = x + (wid > 0 ? wsum[wid - 1] : 0);
    if (i < N_NODES) g_off[i + 1] = incl;
    if (threadIdx.x == 1023) g_bsum[blockIdx.x] = incl;
}

// merged finisher: every block re-scans <=98 block sums, applies prefix,
// writes off/cursor/deginv, and RE-ZEROES g_deg for the next replay.
__global__ void __launch_bounds__(256) k_scan_finish(int nb) {
    __shared__ int spre[128];
    int t = threadIdx.x;
    pdl_wait();                       // dep: k_scan_local writes g_off/g_bsum
    if (t < 128) spre[t] = (t < nb) ? g_bsum[t] : 0;
    __syncthreads();
#pragma unroll
    for (int off = 1; off < 128; off <<= 1) {
        int x = 0;
        if (t < 128 && t >= off) x = spre[t - off];
        __syncthreads();
        if (t < 128) spre[t] += x;
        __syncthreads();
    }
    int i = blockIdx.x * 256 + t;
    if (i < N_NODES) {
        int b = i >> 10;
        int val = g_off[i + 1];
        if (b > 0) val += spre[b - 1];
        g_off[i + 1] = val;
        int d = g_deg[i];
        g_deg[i] = 0;                          // restore invariant for next call
        g_cursor[i] = val - d;                 // == final g_off[i]
        g_deginv[i] = 1.0f / (float)(d > 0 ? d : 1);
    }
    if (i == 0) g_off[0] = 0;
}

// PDL: edge-list loads (independent) issue before the wait; cursor atomics after.
__global__ void k_fill_csr(const int4* __restrict__ src4, const int4* __restrict__ dst4,
                           const float4* __restrict__ e4) {
    int i = blockIdx.x * blockDim.x + threadIdx.x;
    if (i < N_EDGES / 4) {
        int4 s = src4[i];
        int4 d = dst4[i];
        float4 e = e4[i];
        pdl_wait();                   // dep: k_scan_finish writes g_cursor
        int p0 = atomicAdd(&g_cursor[d.x], 1);
        g_csr[p0] = make_int2(s.x, __float_as_int(e.x));
        int p1 = atomicAdd(&g_cursor[d.y], 1);
        g_csr[p1] = make_int2(s.y, __float_as_int(e.y));
        int p2 = atomicAdd(&g_cursor[d.z], 1);
        g_csr[p2] = make_int2(s.z, __float_as_int(e.z));
        int p3 = atomicAdd(&g_cursor[d.w], 1);
        g_csr[p3] = make_int2(s.w, __float_as_int(e.w));
    } else {
        pdl_wait();
    }
}

// ---------------- aggregation layer 1 (round-4 loop). PDL: off/deginv are 2+ kernels
// upstream (safe pre-wait); wait before first g_csr read (dep: k_fill_csr).
__global__ void __launch_bounds__(256) k_agg64(const float* __restrict__ h) {
    int warp = (blockIdx.x * blockDim.x + threadIdx.x) >> 5;
    if (warp >= N_NODES) { pdl_wait(); return; }
    int lane = threadIdx.x & 31;
    int g = lane >> 4;      // edge sub-group 0..1
    int c = lane & 15;      // float4 slot

    int beg = g_off[warp], end = g_off[warp + 1];
    float dinv = g_deginv[warp];
    pdl_wait();                       // dep: k_fill_csr writes g_csr
    float4 acc = make_float4(0.f, 0.f, 0.f, 0.f);
#pragma unroll 4
    for (int p = beg; p < end; p += 2) {
        int pe = p + g;
        if (pe < end) {
            int2 se = g_csr[pe];
            float ev = __int_as_float(se.y);
            float4 r = *(const float4*)(h + (size_t)se.x * F + c * 4);
            acc.x = fmaf(r.x, ev, acc.x);
            acc.y = fmaf(r.y, ev, acc.y);
            acc.z = fmaf(r.z, ev, acc.z);
            acc.w = fmaf(r.w, ev, acc.w);
        }
    }
    acc.x += __shfl_xor_sync(0xffffffff, acc.x, 16);
    acc.y += __shfl_xor_sync(0xffffffff, acc.y, 16);
    acc.z += __shfl_xor_sync(0xffffffff, acc.z, 16);
    acc.w += __shfl_xor_sync(0xffffffff, acc.w, 16);
    if (g == 0) {
        float4 o = make_float4(acc.x * dinv, acc.y * dinv, acc.z * dinv, acc.w * dinv);
        *(float4*)(g_hN + (size_t)warp * F + c * 4) = o;
    }
}

// ---------------- layer-2 aggregation + epilogue. PDL: wait before reading tp2. ----------------
__global__ void __launch_bounds__(256) k_agg32_out(float* __restrict__ out) {
    int warp = (blockIdx.x * blockDim.x + threadIdx.x) >> 5;
    if (warp >= N_NODES) { pdl_wait(); return; }
    int lane = threadIdx.x & 31;
    int g = lane >> 3;      // edge sub-group 0..3
    int c = lane & 7;       // float4 slot

    const float* __restrict__ tp = (const float*)g_hN;

    int beg = g_off[warp], end = g_off[warp + 1];
    float dinv = g_deginv[warp];
    pdl_wait();                       // dep: k_gemm12 writes tp2 (g_hN)
    float4 acc = make_float4(0.f, 0.f, 0.f, 0.f);
#pragma unroll 4
    for (int p = beg; p < end; p += 4) {
        int pe = p + g;
        if (pe < end) {
            int2 se = g_csr[pe];
            float ev = __int_as_float(se.y);
            float4 r = *(const float4*)(tp + (size_t)se.x * 64 + 32 + c * 4);
            acc.x = fmaf(r.x, ev, acc.x);
            acc.y = fmaf(r.y, ev, acc.y);
            acc.z = fmaf(r.z, ev, acc.z);
            acc.w = fmaf(r.w, ev, acc.w);
        }
    }
    acc.x += __shfl_xor_sync(0xffffffff, acc.x, 8);
    acc.y += __shfl_xor_sync(0xffffffff, acc.y, 8);
    acc.z += __shfl_xor_sync(0xffffffff, acc.z, 8);
    acc.w += __shfl_xor_sync(0xffffffff, acc.w, 8);
    acc.x += __shfl_xor_sync(0xffffffff, acc.x, 16);
    acc.y += __shfl_xor_sync(0xffffffff, acc.y, 16);
    acc.z += __shfl_xor_sync(0xffffffff, acc.z, 16);
    acc.w += __shfl_xor_sync(0xffffffff, acc.w, 16);
    if (g == 0) {
        float4 t = *(const float4*)(tp + (size_t)warp * 64 + c * 4);
        float4 o = make_float4(t.x + acc.x * dinv, t.y + acc.y * dinv,
                               t.z + acc.z * dinv, t.w + acc.w * dinv);
        *(float4*)(out + (size_t)warp * 32 + c * 4) = o;
    }
}

// ---------------- P-GEMM (overlapped with CSR build, normal launch) ----------------
__global__ void __launch_bounds__(256) k_gemmP(const float* __restrict__ A0,
                                               const float* __restrict__ W1,
                                               const float* __restrict__ b1) {
    constexpr int NOUT = 64;
    constexpr int BM = 64;
    constexpr int JG = 16;
    constexpr int NT = 256;
    constexpr int AP = 68;

    __shared__ __align__(16) float sA[BM * AP];
    __shared__ __align__(16) float sW[64 * NOUT];

    int tid = threadIdx.x;
    int m0  = blockIdx.x * BM;
    int jg  = tid % JG;
    int ng  = tid / JG;

    unsigned long long acc[4][2];
    {
        ulonglong2 b2v = *(const ulonglong2*)(b1 + jg * 4);
#pragma unroll
        for (int i = 0; i < 4; i++) { acc[i][0] = b2v.x; acc[i][1] = b2v.y; }
    }

    for (int idx = tid; idx < BM * 16; idx += NT) {
        int m = idx >> 4, kq = idx & 15;
        int gm = m0 + m;
        float4 v = make_float4(0.f, 0.f, 0.f, 0.f);
        if (gm < N_NODES) v = *(const float4*)(A0 + (size_t)gm * F + kq * 4);
        *(float4*)(sA + m * AP + kq * 4) = v;
    }
    for (int idx = tid; idx < 64 * NOUT / 4; idx += NT)
        *(float4*)(sW + idx * 4) = *(const float4*)(W1 + idx * 4);   // rows 0..63
    __syncthreads();

    const float* a_base = sA + (ng * 4) * AP;
#pragma unroll 8
    for (int k = 0; k < 64; ++k) {
        ulonglong2 w2 = *(const ulonglong2*)(sW + k * NOUT + jg * 4);
        unsigned long long a0 = pack2(a_base[k]);
        unsigned long long a1 = pack2(a_base[AP + k]);
        unsigned long long a2 = pack2(a_base[2 * AP + k]);
        unsigned long long a3 = pack2(a_base[3 * AP + k]);
        ffma2(acc[0][0], a0, w2.x); ffma2(acc[0][1], a0, w2.y);
        ffma2(acc[1][0], a1, w2.x); ffma2(acc[1][1], a1, w2.y);
        ffma2(acc[2][0], a2, w2.x); ffma2(acc[2][1], a2, w2.y);
        ffma2(acc[3][0], a3, w2.x); ffma2(acc[3][1], a3, w2.y);
    }

#pragma unroll
    for (int i = 0; i < 4; i++) {
        int gm = m0 + ng * 4 + i;
        if (gm < N_NODES) {
            float2 lo = unpack2(acc[i][0]);
            float2 hi = unpack2(acc[i][1]);
            *(float4*)(g_P + (size_t)gm * F + jg * 4) = make_float4(lo.x, lo.y, hi.x, hi.y);
        }
    }
}

// ---------------- fused GEMM. PDL: W1 staging pre-wait; g_P/g_hN reads post-wait. ----------------
__global__ void __launch_bounds__(256) k_gemm12(const float* __restrict__ W1,
                                                const float* __restrict__ W2,
                                                const float* __restrict__ b2) {
    constexpr int NOUT = 64;
    constexpr int BM = 64;
    constexpr int JG = 16;
    constexpr int NT = 256;
    constexpr int AP = 68;

    __shared__ __align__(16) float sA[BM * AP];
    __shared__ __align__(16) float sW[64 * NOUT];

    int tid = threadIdx.x;
    int m0  = blockIdx.x * BM;
    int jg  = tid % JG;
    int ng  = tid / JG;

    // independent prologue: stage W1 rows 64..127
    for (int idx = tid; idx < 64 * NOUT / 4; idx += NT)
        *(float4*)(sW + idx * 4) = *(const float4*)(W1 + 64 * 64 + idx * 4);

    pdl_wait();                       // dep: k_agg64 writes g_hN (g_P via hard event edge)

    // ---- phase 1: h1 = relu(P + hN @ W1_bot) ----
    unsigned long long acc[4][2];
#pragma unroll
    for (int i = 0; i < 4; i++) {
        int gm = m0 + ng * 4 + i;
        if (gm < N_NODES) {
            ulonglong2 p = *(const ulonglong2*)(g_P + (size_t)gm * F + jg * 4);
            acc[i][0] = p.x; acc[i][1] = p.y;
        } else {
            acc[i][0] = 0ull; acc[i][1] = 0ull;
        }
    }

    for (int idx = tid; idx < BM * 16; idx += NT) {
        int m = idx >> 4, kq = idx & 15;
        int gm = m0 + m;
        float4 v = make_float4(0.f, 0.f, 0.f, 0.f);
        if (gm < N_NODES) v = *(const float4*)(g_hN + (size_t)gm * F + kq * 4);
        *(float4*)(sA + m * AP + kq * 4) = v;
    }
    __syncthreads();

    const float* a_base = sA + (ng * 4) * AP;
#pragma unroll 8
    for (int k = 0; k < 64; ++k) {
        ulonglong2 w2 = *(const ulonglong2*)(sW + k * NOUT + jg * 4);
        unsigned long long a0 = pack2(a_base[k]);
        unsigned long long a1 = pack2(a_base[AP + k]);
        unsigned long long a2 = pack2(a_base[2 * AP + k]);
        unsigned long long a3 = pack2(a_base[3 * AP + k]);
        ffma2(acc[0][0], a0, w2.x); ffma2(acc[0][1], a0, w2.y);
        ffma2(acc[1][0], a1, w2.x); ffma2(acc[1][1], a1, w2.y);
        ffma2(acc[2][0], a2, w2.x); ffma2(acc[2][1], a2, w2.y);
        ffma2(acc[3][0], a3, w2.x); ffma2(acc[3][1], a3, w2.y);
    }
    __syncthreads();   // all reads of sA(hN) done

    // write relu(h1) into sA; reload sW with combined W2
#pragma unroll
    for (int i = 0; i < 4; i++) {
        float2 lo = unpack2(acc[i][0]);
        float2 hi = unpack2(acc[i][1]);
        float4 o = make_float4(fmaxf(lo.x, 0.f), fmaxf(lo.y, 0.f),
                               fmaxf(hi.x, 0.f), fmaxf(hi.y, 0.f));
        *(float4*)(sA + (ng * 4 + i) * AP + jg * 4) = o;
    }
    for (int idx = tid; idx < 64 * NOUT / 4; idx += NT) {
        int k = idx >> 4, jq = idx & 15;
        float4 v;
        if (jq < 8) v = *(const float4*)(W2 + k * 32 + jq * 4);
        else        v = *(const float4*)(W2 + (64 + k) * 32 + (jq - 8) * 4);
        *(float4*)(sW + k * NOUT + jq * 4) = v;
    }
    __syncthreads();

    // ---- phase 2: tp2 = [h1@W2_top + b2 | h1@W2_bot] ----
    unsigned long long acc2[4][2];
    if (jg < 8) {
        ulonglong2 b2v = *(const ulonglong2*)(b2 + jg * 4);
#pragma unroll
        for (int i = 0; i < 4; i++) { acc2[i][0] = b2v.x; acc2[i][1] = b2v.y; }
    } else {
#pragma unroll
        for (int i = 0; i < 4; i++) { acc2[i][0] = 0ull; acc2[i][1] = 0ull; }
    }

#pragma unroll 8
    for (int k = 0; k < 64; ++k) {
        ulonglong2 w2 = *(const ulonglong2*)(sW + k * NOUT + jg * 4);
        unsigned long long a0 = pack2(a_base[k]);
        unsigned long long a1 = pack2(a_base[AP + k]);
        unsigned long long a2 = pack2(a_base[2 * AP + k]);
        unsigned long long a3 = pack2(a_base[3 * AP + k]);
        ffma2(acc2[0][0], a0, w2.x); ffma2(acc2[0][1], a0, w2.y);
        ffma2(acc2[1][0], a1, w2.x); ffma2(acc2[1][1], a1, w2.y);
        ffma2(acc2[2][0], a2, w2.x); ffma2(acc2[2][1], a2, w2.y);
        ffma2(acc2[3][0], a3, w2.x); ffma2(acc2[3][1], a3, w2.y);
    }

#pragma unroll
    for (int i = 0; i < 4; i++) {
        int gm = m0 + ng * 4 + i;
        if (gm < N_NODES) {
            float2 lo = unpack2(acc2[i][0]);
            float2 hi = unpack2(acc2[i][1]);
            *(float4*)(g_hN + (size_t)gm * NOUT + jg * 4) = make_float4(lo.x, lo.y, hi.x, hi.y);
        }
    }
}

// ---------------- launch ----------------
extern "C" void kernel_launch(void* const* d_in, const int* in_sizes, int n_in,
                              void* d_out, int out_size) {
    const float* in_feat   = (const float*)d_in[0];
    const float* edge_feat = (const float*)d_in[1];
    const int*   src       = (const int*)d_in[2];
    const int*   dst       = (const int*)d_in[3];
    const float* W1        = (const float*)d_in[4];
    const float* b1        = (const float*)d_in[5];
    const float* W2        = (const float*)d_in[6];
    const float* b2        = (const float*)d_in[7];
    float*       out       = (float*)d_out;

    // one-time host resources (created on the non-captured correctness call)
    static cudaStream_t s2 = nullptr;
    static cudaEvent_t ev0 = nullptr, ev1 = nullptr;
    if (s2 == nullptr) {
        cudaStreamCreateWithFlags(&s2, cudaStreamNonBlocking);
        cudaEventCreateWithFlags(&ev0, cudaEventDisableTiming);
        cudaEventCreateWithFlags(&ev1, cudaEventDisableTiming);
    }

    const int nodeBlocks  = (N_NODES + 255) / 256;
    const int edge4Blocks = (N_EDGES / 4 + 255) / 256;
    const int scanBlocks  = (N_NODES + 1023) / 1024;
    const int aggBlocks   = (N_NODES * 32 + 255) / 256;
    const int gemmBlocks  = (N_NODES + 63) / 64;

    // PDL launch config (programmatic stream serialization)
    cudaLaunchAttribute pdlAttr{};
    pdlAttr.id = cudaLaunchAttributeProgrammaticStreamSerialization;
    pdlAttr.val.programmaticStreamSerializationAllowed = 1;
    cudaLaunchConfig_t cfg{};
    cfg.stream = 0;
    cfg.attrs = &pdlAttr;
    cfg.numAttrs = 1;

    // fork: P = in @ W1_top + b1 (no CSR dependency) on s2
    cudaEventRecord(ev0, 0);
    cudaStreamWaitEvent(s2, ev0, 0);
    k_gemmP<<<gemmBlocks, 256, 0, s2>>>(in_feat, W1, b1);
    cudaEventRecord(ev1, s2);

    // CSR build chain (main stream, PDL-chained; g_deg pre-zeroed invariant)
    k_deg<<<edge4Blocks, 256>>>((const int4*)dst);

    cfg.gridDim = dim3(scanBlocks); cfg.blockDim = dim3(1024);
    cudaLaunchKernelEx(&cfg, k_scan_local);

    cfg.gridDim = dim3(nodeBlocks); cfg.blockDim = dim3(256);
    cudaLaunchKernelEx(&cfg, k_scan_finish, (int)scanBlocks);

    cfg.gridDim = dim3(edge4Blocks); cfg.blockDim = dim3(256);
    cudaLaunchKernelEx(&cfg, k_fill_csr,
                       (const int4*)src, (const int4*)dst, (const float4*)edge_feat);

    cfg.gridDim = dim3(aggBlocks); cfg.blockDim = dim3(256);
    cudaLaunchKernelEx(&cfg, k_agg64, in_feat);

    // join: fused GEMM needs hN (PDL) + P (hard event edge)
    cudaStreamWaitEvent(0, ev1, 0);
    cfg.gridDim = dim3(gemmBlocks); cfg.blockDim = dim3(256);
    cudaLaunchKernelEx(&cfg, k_gemm12, W1, W2, b2);

    cfg.gridDim = dim3(aggBlocks); cfg.blockDim = dim3(256);
    cudaLaunchKernelEx(&cfg, k_agg32_out, out);
}

// round 17
// speedup vs baseline: 1.0269x; 1.0269x over previous
#include <cuda_runtime.h>
#include <cstdint>

#define N_NODES 100000
#define N_EDGES 1600000
#define F 64

// ---------------- static device scratch ----------------
__device__ int   g_deg[N_NODES];
__device__ int   g_off[N_NODES + 1];
__device__ int   g_cursor[N_NODES];
__device__ int   g_bsum[128];
__device__ int2  g_csr[N_EDGES];              // packed {src, float_bits(e)}
__device__ float g_deginv[N_NODES];
__device__ float g_hN[(size_t)N_NODES * F];   // hN (layer1) -> tp2 (layer2, in-place)
__device__ float g_P[(size_t)N_NODES * F];    // P = in@W1_top + b1 (overlapped)

// ---------------- helpers ----------------
__device__ __forceinline__ void pdl_wait() {
    asm volatile("griddepcontrol.wait;" ::: "memory");
}
__device__ __forceinline__ unsigned long long pack2(float a) {
    unsigned long long r;
    asm("mov.b64 %0, {%1, %1};" : "=l"(r) : "f"(a));
    return r;
}
__device__ __forceinline__ void ffma2(unsigned long long& d,
                                      unsigned long long a, unsigned long long b) {
    asm("fma.rn.f32x2 %0, %1, %2, %0;" : "+l"(d) : "l"(a), "l"(b));
}
__device__ __forceinline__ float2 unpack2(unsigned long long v) {
    float lo, hi;
    asm("mov.b64 {%0, %1}, %2;" : "=f"(lo), "=f"(hi) : "l"(v));
    return make_float2(lo, hi);
}

// ---------------- CSR build ----------------
__global__ void k_deg(const int4* __restrict__ dst4) {
    int i = blockIdx.x * blockDim.x + threadIdx.x;
    if (i < N_EDGES / 4) {
        int4 d = dst4[i];
        atomicAdd(&g_deg[d.x], 1);
        atomicAdd(&g_deg[d.y], 1);
        atomicAdd(&g_deg[d.z], 1);
        atomicAdd(&g_deg[d.w], 1);
    }
}

// warp-shuffle scan (2 syncthreads). PDL: waits before reading g_deg.
__global__ void __launch_bounds__(1024) k_scan_local() {
    __shared__ int wsum[32];
    int i = blockIdx.x * 1024 + threadIdx.x;
    int lane = threadIdx.x & 31, wid = threadIdx.x >> 5;
    pdl_wait();                       // dep: k_deg writes g_deg
    int v = (i < N_NODES) ? g_deg[i] : 0;
    int x = v;
#pragma unroll
    for (int o = 1; o < 32; o <<= 1) {
        int y = __shfl_up_sync(0xffffffff, x, o);
        if (lane >= o) x += y;
    }
    if (lane == 31) wsum[wid] = x;
    __syncthreads();
    if (wid == 0) {
        int s = wsum[lane];
#pragma unroll
        for (int o = 1; o < 32; o <<= 1) {
            int y = __shfl_up_sync(0xffffffff, s, o);
            if (lane >= o) s += y;
        }
        wsum[lane] = s;
    }
    __syncthreads();
    int incl = x + (wid > 0 ? wsum[wid - 1] : 0);
    if (i < N_NODES) g_off[i + 1] = incl;
    if (threadIdx.x == 1023) g_bsum[blockIdx.x] = incl;
}

// merged finisher (round-13): every block re-scans <=98 block sums, applies prefix.
__global__ void __launch_bounds__(256) k_scan_finish(int nb) {
    __shared__ int spre[128];
    int t = threadIdx.x;
    pdl_wait();                       // dep: k_scan_local writes g_off/g_bsum
    if (t < 128) spre[t] = (t < nb) ? g_bsum[t] : 0;
    __syncthreads();
#pragma unroll
    for (int off = 1; off < 128; off <<= 1) {
        int x = 0;
        if (t < 128 && t >= off) x = spre[t - off];
        __syncthreads();
        if (t < 128) spre[t] += x;
        __syncthreads();
    }
    int i = blockIdx.x * 256 + t;
    if (i < N_NODES) {
        int b = i >> 10;
        int val = g_off[i + 1];
        if (b > 0) val += spre[b - 1];
        g_off[i + 1] = val;
        int d = g_deg[i];
        g_cursor[i] = val - d;                 // == final g_off[i]
        g_deginv[i] = 1.0f / (float)(d > 0 ? d : 1);
    }
    if (i == 0) g_off[0] = 0;
}

// PDL: edge-list loads (independent) issue before the wait; cursor atomics after.
__global__ void k_fill_csr(const int4* __restrict__ src4, const int4* __restrict__ dst4,
                           const float4* __restrict__ e4) {
    int i = blockIdx.x * blockDim.x + threadIdx.x;
    if (i < N_EDGES / 4) {
        int4 s = src4[i];
        int4 d = dst4[i];
        float4 e = e4[i];
        pdl_wait();                   // dep: k_scan_finish writes g_cursor
        int p0 = atomicAdd(&g_cursor[d.x], 1);
        g_csr[p0] = make_int2(s.x, __float_as_int(e.x));
        int p1 = atomicAdd(&g_cursor[d.y], 1);
        g_csr[p1] = make_int2(s.y, __float_as_int(e.y));
        int p2 = atomicAdd(&g_cursor[d.z], 1);
        g_csr[p2] = make_int2(s.z, __float_as_int(e.z));
        int p3 = atomicAdd(&g_cursor[d.w], 1);
        g_csr[p3] = make_int2(s.w, __float_as_int(e.w));
    } else {
        pdl_wait();
    }
}

// ---------------- aggregation layer 1 (round-4 loop). PDL: off/deginv are 2+ kernels
// upstream (safe pre-wait); wait before first g_csr read (dep: k_fill_csr).
__global__ void __launch_bounds__(256) k_agg64(const float* __restrict__ h) {
    int warp = (blockIdx.x * blockDim.x + threadIdx.x) >> 5;
    if (warp >= N_NODES) { pdl_wait(); return; }
    int lane = threadIdx.x & 31;
    int g = lane >> 4;      // edge sub-group 0..1
    int c = lane & 15;      // float4 slot

    int beg = g_off[warp], end = g_off[warp + 1];
    float dinv = g_deginv[warp];
    pdl_wait();                       // dep: k_fill_csr writes g_csr
    float4 acc = make_float4(0.f, 0.f, 0.f, 0.f);
#pragma unroll 4
    for (int p = beg; p < end; p += 2) {
        int pe = p + g;
        if (pe < end) {
            int2 se = g_csr[pe];
            float ev = __int_as_float(se.y);
            float4 r = *(const float4*)(h + (size_t)se.x * F + c * 4);
            acc.x = fmaf(r.x, ev, acc.x);
            acc.y = fmaf(r.y, ev, acc.y);
            acc.z = fmaf(r.z, ev, acc.z);
            acc.w = fmaf(r.w, ev, acc.w);
        }
    }
    acc.x += __shfl_xor_sync(0xffffffff, acc.x, 16);
    acc.y += __shfl_xor_sync(0xffffffff, acc.y, 16);
    acc.z += __shfl_xor_sync(0xffffffff, acc.z, 16);
    acc.w += __shfl_xor_sync(0xffffffff, acc.w, 16);
    if (g == 0) {
        float4 o = make_float4(acc.x * dinv, acc.y * dinv, acc.z * dinv, acc.w * dinv);
        *(float4*)(g_hN + (size_t)warp * F + c * 4) = o;
    }
}

// ---------------- layer-2 aggregation + epilogue. PDL: wait before reading tp2. ----------------
__global__ void __launch_bounds__(256) k_agg32_out(float* __restrict__ out) {
    int warp = (blockIdx.x * blockDim.x + threadIdx.x) >> 5;
    if (warp >= N_NODES) { pdl_wait(); return; }
    int lane = threadIdx.x & 31;
    int g = lane >> 3;      // edge sub-group 0..3
    int c = lane & 7;       // float4 slot

    const float* __restrict__ tp = (const float*)g_hN;

    int beg = g_off[warp], end = g_off[warp + 1];
    float dinv = g_deginv[warp];
    pdl_wait();                       // dep: k_gemm12 writes tp2 (g_hN)
    float4 acc = make_float4(0.f, 0.f, 0.f, 0.f);
#pragma unroll 4
    for (int p = beg; p < end; p += 4) {
        int pe = p + g;
        if (pe < end) {
            int2 se = g_csr[pe];
            float ev = __int_as_float(se.y);
            float4 r = *(const float4*)(tp + (size_t)se.x * 64 + 32 + c * 4);
            acc.x = fmaf(r.x, ev, acc.x);
            acc.y = fmaf(r.y, ev, acc.y);
            acc.z = fmaf(r.z, ev, acc.z);
            acc.w = fmaf(r.w, ev, acc.w);
        }
    }
    acc.x += __shfl_xor_sync(0xffffffff, acc.x, 8);
    acc.y += __shfl_xor_sync(0xffffffff, acc.y, 8);
    acc.z += __shfl_xor_sync(0xffffffff, acc.z, 8);
    acc.w += __shfl_xor_sync(0xffffffff, acc.w, 8);
    acc.x += __shfl_xor_sync(0xffffffff, acc.x, 16);
    acc.y += __shfl_xor_sync(0xffffffff, acc.y, 16);
    acc.z += __shfl_xor_sync(0xffffffff, acc.z, 16);
    acc.w += __shfl_xor_sync(0xffffffff, acc.w, 16);
    if (g == 0) {
        float4 t = *(const float4*)(tp + (size_t)warp * 64 + c * 4);
        float4 o = make_float4(t.x + acc.x * dinv, t.y + acc.y * dinv,
                               t.z + acc.z * dinv, t.w + acc.w * dinv);
        *(float4*)(out + (size_t)warp * 32 + c * 4) = o;
    }
}

// ---------------- P-GEMM (overlapped with CSR build, normal launch) ----------------
__global__ void __launch_bounds__(256) k_gemmP(const float* __restrict__ A0,
                                               const float* __restrict__ W1,
                                               const float* __restrict__ b1) {
    constexpr int NOUT = 64;
    constexpr int BM = 64;
    constexpr int JG = 16;
    constexpr int NT = 256;
    constexpr int AP = 68;

    __shared__ __align__(16) float sA[BM * AP];
    __shared__ __align__(16) float sW[64 * NOUT];

    int tid = threadIdx.x;
    int m0  = blockIdx.x * BM;
    int jg  = tid % JG;
    int ng  = tid / JG;

    unsigned long long acc[4][2];
    {
        ulonglong2 b2v = *(const ulonglong2*)(b1 + jg * 4);
#pragma unroll
        for (int i = 0; i < 4; i++) { acc[i][0] = b2v.x; acc[i][1] = b2v.y; }
    }

    for (int idx = tid; idx < BM * 16; idx += NT) {
        int m = idx >> 4, kq = idx & 15;
        int gm = m0 + m;
        float4 v = make_float4(0.f, 0.f, 0.f, 0.f);
        if (gm < N_NODES) v = *(const float4*)(A0 + (size_t)gm * F + kq * 4);
        *(float4*)(sA + m * AP + kq * 4) = v;
    }
    for (int idx = tid; idx < 64 * NOUT / 4; idx += NT)
        *(float4*)(sW + idx * 4) = *(const float4*)(W1 + idx * 4);   // rows 0..63
    __syncthreads();

    const float* a_base = sA + (ng * 4) * AP;
#pragma unroll 8
    for (int k = 0; k < 64; ++k) {
        ulonglong2 w2 = *(const ulonglong2*)(sW + k * NOUT + jg * 4);
        unsigned long long a0 = pack2(a_base[k]);
        unsigned long long a1 = pack2(a_base[AP + k]);
        unsigned long long a2 = pack2(a_base[2 * AP + k]);
        unsigned long long a3 = pack2(a_base[3 * AP + k]);
        ffma2(acc[0][0], a0, w2.x); ffma2(acc[0][1], a0, w2.y);
        ffma2(acc[1][0], a1, w2.x); ffma2(acc[1][1], a1, w2.y);
        ffma2(acc[2][0], a2, w2.x); ffma2(acc[2][1], a2, w2.y);
        ffma2(acc[3][0], a3, w2.x); ffma2(acc[3][1], a3, w2.y);
    }

#pragma unroll
    for (int i = 0; i < 4; i++) {
        int gm = m0 + ng * 4 + i;
        if (gm < N_NODES) {
            float2 lo = unpack2(acc[i][0]);
            float2 hi = unpack2(acc[i][1]);
            *(float4*)(g_P + (size_t)gm * F + jg * 4) = make_float4(lo.x, lo.y, hi.x, hi.y);
        }
    }
}

// ---------------- fused GEMM. PDL: W1 staging pre-wait; g_P/g_hN reads post-wait. ----------------
__global__ void __launch_bounds__(256) k_gemm12(const float* __restrict__ W1,
                                                const float* __restrict__ W2,
                                                const float* __restrict__ b2) {
    constexpr int NOUT = 64;
    constexpr int BM = 64;
    constexpr int JG = 16;
    constexpr int NT = 256;
    constexpr int AP = 68;

    __shared__ __align__(16) float sA[BM * AP];
    __shared__ __align__(16) float sW[64 * NOUT];

    int tid = threadIdx.x;
    int m0  = blockIdx.x * BM;
    int jg  = tid % JG;
    int ng  = tid / JG;

    // independent prologue: stage W1 rows 64..127
    for (int idx = tid; idx < 64 * NOUT / 4; idx += NT)
        *(float4*)(sW + idx * 4) = *(const float4*)(W1 + 64 * 64 + idx * 4);

    pdl_wait();                       // dep: k_agg64 writes g_hN (g_P via earlier event edge)

    // ---- phase 1: h1 = relu(P + hN @ W1_bot) ----
    unsigned long long acc[4][2];
#pragma unroll
    for (int i = 0; i < 4; i++) {
        int gm = m0 + ng * 4 + i;
        if (gm < N_NODES) {
            ulonglong2 p = *(const ulonglong2*)(g_P + (size_t)gm * F + jg * 4);
            acc[i][0] = p.x; acc[i][1] = p.y;
        } else {
            acc[i][0] = 0ull; acc[i][1] = 0ull;
        }
    }

    for (int idx = tid; idx < BM * 16; idx += NT) {
        int m = idx >> 4, kq = idx & 15;
        int gm = m0 + m;
        float4 v = make_float4(0.f, 0.f, 0.f, 0.f);
        if (gm < N_NODES) v = *(const float4*)(g_hN + (size_t)gm * F + kq * 4);
        *(float4*)(sA + m * AP + kq * 4) = v;
    }
    __syncthreads();

    const float* a_base = sA + (ng * 4) * AP;
#pragma unroll 8
    for (int k = 0; k < 64; ++k) {
        ulonglong2 w2 = *(const ulonglong2*)(sW + k * NOUT + jg * 4);
        unsigned long long a0 = pack2(a_base[k]);
        unsigned long long a1 = pack2(a_base[AP + k]);
        unsigned long long a2 = pack2(a_base[2 * AP + k]);
        unsigned long long a3 = pack2(a_base[3 * AP + k]);
        ffma2(acc[0][0], a0, w2.x); ffma2(acc[0][1], a0, w2.y);
        ffma2(acc[1][0], a1, w2.x); ffma2(acc[1][1], a1, w2.y);
        ffma2(acc[2][0], a2, w2.x); ffma2(acc[2][1], a2, w2.y);
        ffma2(acc[3][0], a3, w2.x); ffma2(acc[3][1], a3, w2.y);
    }
    __syncthreads();   // all reads of sA(hN) done

    // write relu(h1) into sA; reload sW with combined W2
#pragma unroll
    for (int i = 0; i < 4; i++) {
        float2 lo = unpack2(acc[i][0]);
        float2 hi = unpack2(acc[i][1]);
        float4 o = make_float4(fmaxf(lo.x, 0.f), fmaxf(lo.y, 0.f),
                               fmaxf(hi.x, 0.f), fmaxf(hi.y, 0.f));
        *(float4*)(sA + (ng * 4 + i) * AP + jg * 4) = o;
    }
    for (int idx = tid; idx < 64 * NOUT / 4; idx += NT) {
        int k = idx >> 4, jq = idx & 15;
        float4 v;
        if (jq < 8) v = *(const float4*)(W2 + k * 32 + jq * 4);
        else        v = *(const float4*)(W2 + (64 + k) * 32 + (jq - 8) * 4);
        *(float4*)(sW + k * NOUT + jq * 4) = v;
    }
    __syncthreads();

    // ---- phase 2: tp2 = [h1@W2_top + b2 | h1@W2_bot] ----
    unsigned long long acc2[4][2];
    if (jg < 8) {
        ulonglong2 b2v = *(const ulonglong2*)(b2 + jg * 4);
#pragma unroll
        for (int i = 0; i < 4; i++) { acc2[i][0] = b2v.x; acc2[i][1] = b2v.y; }
    } else {
#pragma unroll
        for (int i = 0; i < 4; i++) { acc2[i][0] = 0ull; acc2[i][1] = 0ull; }
    }

#pragma unroll 8
    for (int k = 0; k < 64; ++k) {
        ulonglong2 w2 = *(const ulonglong2*)(sW + k * NOUT + jg * 4);
        unsigned long long a0 = pack2(a_base[k]);
        unsigned long long a1 = pack2(a_base[AP + k]);
        unsigned long long a2 = pack2(a_base[2 * AP + k]);
        unsigned long long a3 = pack2(a_base[3 * AP + k]);
        ffma2(acc2[0][0], a0, w2.x); ffma2(acc2[0][1], a0, w2.y);
        ffma2(acc2[1][0], a1, w2.x); ffma2(acc2[1][1], a1, w2.y);
        ffma2(acc2[2][0], a2, w2.x); ffma2(acc2[2][1], a2, w2.y);
        ffma2(acc2[3][0], a3, w2.x); ffma2(acc2[3][1], a3, w2.y);
    }

#pragma unroll
    for (int i = 0; i < 4; i++) {
        int gm = m0 + ng * 4 + i;
        if (gm < N_NODES) {
            float2 lo = unpack2(acc2[i][0]);
            float2 hi = unpack2(acc2[i][1]);
            *(float4*)(g_hN + (size_t)gm * NOUT + jg * 4) = make_float4(lo.x, lo.y, hi.x, hi.y);
        }
    }
}

// ---------------- launch ----------------
extern "C" void kernel_launch(void* const* d_in, const int* in_sizes, int n_in,
                              void* d_out, int out_size) {
    const float* in_feat   = (const float*)d_in[0];
    const float* edge_feat = (const float*)d_in[1];
    const int*   src       = (const int*)d_in[2];
    const int*   dst       = (const int*)d_in[3];
    const float* W1        = (const float*)d_in[4];
    const float* b1        = (const float*)d_in[5];
    const float* W2        = (const float*)d_in[6];
    const float* b2        = (const float*)d_in[7];
    float*       out       = (float*)d_out;

    // one-time host resources (created on the non-captured correctness call)
    static cudaStream_t s2 = nullptr;
    static cudaEvent_t ev0 = nullptr, ev1 = nullptr;
    if (s2 == nullptr) {
        cudaStreamCreateWithFlags(&s2, cudaStreamNonBlocking);
        cudaEventCreateWithFlags(&ev0, cudaEventDisableTiming);
        cudaEventCreateWithFlags(&ev1, cudaEventDisableTiming);
    }

    const int nodeBlocks  = (N_NODES + 255) / 256;
    const int edge4Blocks = (N_EDGES / 4 + 255) / 256;
    const int scanBlocks  = (N_NODES + 1023) / 1024;
    const int aggBlocks   = (N_NODES * 32 + 255) / 256;
    const int gemmBlocks  = (N_NODES + 63) / 64;

    // PDL launch config (programmatic stream serialization)
    cudaLaunchAttribute pdlAttr{};
    pdlAttr.id = cudaLaunchAttributeProgrammaticStreamSerialization;
    pdlAttr.val.programmaticStreamSerializationAllowed = 1;
    cudaLaunchConfig_t cfg{};
    cfg.stream = 0;
    cfg.attrs = &pdlAttr;
    cfg.numAttrs = 1;

    // zero degree via memset DMA node (no kernel launch)
    void* degPtr = nullptr;
    cudaGetSymbolAddress(&degPtr, g_deg);
    cudaMemsetAsync(degPtr, 0, N_NODES * sizeof(int));

    // fork: P = in @ W1_top + b1 (no CSR dependency) on s2
    cudaEventRecord(ev0, 0);
    cudaStreamWaitEvent(s2, ev0, 0);
    k_gemmP<<<gemmBlocks, 256, 0, s2>>>(in_feat, W1, b1);
    cudaEventRecord(ev1, s2);

    // CSR build chain (main stream, PDL-chained)
    k_deg<<<edge4Blocks, 256>>>((const int4*)dst);

    cfg.gridDim = dim3(scanBlocks); cfg.blockDim = dim3(1024);
    cudaLaunchKernelEx(&cfg, k_scan_local);

    cfg.gridDim = dim3(nodeBlocks); cfg.blockDim = dim3(256);
    cudaLaunchKernelEx(&cfg, k_scan_finish, (int)scanBlocks);

    cfg.gridDim = dim3(edge4Blocks); cfg.blockDim = dim3(256);
    cudaLaunchKernelEx(&cfg, k_fill_csr,
                       (const int4*)src, (const int4*)dst, (const float4*)edge_feat);

    // join moved EARLY: ev1 is long-signaled by now (gemmP ran at t=0); placing it
    // here keeps the agg64 -> gemm12 boundary a pure PDL edge (no event node between).
    cudaStreamWaitEvent(0, ev1, 0);

    cfg.gridDim = dim3(aggBlocks); cfg.blockDim = dim3(256);
    cudaLaunchKernelEx(&cfg, k_agg64, in_feat);

    cfg.gridDim = dim3(gemmBlocks); cfg.blockDim = dim3(256);
    cudaLaunchKernelEx(&cfg, k_gemm12, W1, W2, b2);

    cfg.gridDim = dim3(aggBlocks); cfg.blockDim = dim3(256);
    cudaLaunchKernelEx(&cfg, k_agg32_out, out);
}